// round 2
// baseline (speedup 1.0000x reference)
#include <cuda_runtime.h>
#include <cstdint>
#include <cstddef>

#define NN   8192
#define FIN  256
#define FOUT 128
#define MT   64      // rows per CTA in main kernel
#define JT   128     // j-tile
#define SPS  136     // sP row stride (mod 32 = 8 -> conflict-free frag loads)
#define SBS  136     // sB row stride

// ---- scratch (static device memory; no allocation) ----
__device__ float g_Wh[NN * FOUT];       // 4 MB
__device__ float g_ssrc[NN];
__device__ float g_usrc[NN];
__device__ float g_u5src[NN];
__device__ float g_sdst[NN];
__device__ float g_vdst[NN];
__device__ float g_v5dst[NN];

__device__ __forceinline__ float to_tf32(float x) {
    unsigned r;
    asm("cvt.rna.tf32.f32 %0, %1;" : "=r"(r) : "f"(x));
    return __uint_as_float(r);
}

// ---------------- Phase 1: Wh = h @ W^T  (fp32 SIMT GEMM) ----------------
__global__ void __launch_bounds__(256) k_wh(const float* __restrict__ h,
                                            const float* __restrict__ W) {
    __shared__ float sH[32][68];    // [k][i], 64 rows
    __shared__ float sW[32][132];   // [k][f], 128 cols
    const int t  = threadIdx.x;
    const int i0 = blockIdx.x * MT;
    const int rb = (t >> 5) * 8;    // 8 rows per thread (warp-broadcast A)
    const int cb = (t & 31) * 4;    // 4 cols per thread

    float acc[8][4];
#pragma unroll
    for (int r = 0; r < 8; r++)
#pragma unroll
        for (int c = 0; c < 4; c++) acc[r][c] = 0.f;

    for (int k0 = 0; k0 < FIN; k0 += 32) {
        __syncthreads();
#pragma unroll
        for (int it = 0; it < 2; it++) {
            int idx = t + 256 * it;          // 512 float4 of h tile
            int row = idx >> 3;
            int kc  = (idx & 7) * 4;
            float4 v = *reinterpret_cast<const float4*>(h + (size_t)(i0 + row) * FIN + k0 + kc);
            sH[kc + 0][row] = v.x; sH[kc + 1][row] = v.y;
            sH[kc + 2][row] = v.z; sH[kc + 3][row] = v.w;
        }
#pragma unroll
        for (int it = 0; it < 4; it++) {
            int idx = t + 256 * it;          // 1024 float4 of W tile
            int f   = idx >> 3;
            int kc  = (idx & 7) * 4;
            float4 v = *reinterpret_cast<const float4*>(W + (size_t)f * FIN + k0 + kc);
            sW[kc + 0][f] = v.x; sW[kc + 1][f] = v.y;
            sW[kc + 2][f] = v.z; sW[kc + 3][f] = v.w;
        }
        __syncthreads();
#pragma unroll
        for (int k = 0; k < 32; k++) {
            float a[8], b[4];
            *reinterpret_cast<float4*>(a)     = *reinterpret_cast<const float4*>(&sH[k][rb]);
            *reinterpret_cast<float4*>(a + 4) = *reinterpret_cast<const float4*>(&sH[k][rb + 4]);
            *reinterpret_cast<float4*>(b)     = *reinterpret_cast<const float4*>(&sW[k][cb]);
#pragma unroll
            for (int r = 0; r < 8; r++)
#pragma unroll
                for (int c = 0; c < 4; c++) acc[r][c] = fmaf(a[r], b[c], acc[r][c]);
        }
    }
#pragma unroll
    for (int r = 0; r < 8; r++) {
        float4 v = make_float4(acc[r][0], acc[r][1], acc[r][2], acc[r][3]);
        *reinterpret_cast<float4*>(g_Wh + (size_t)(i0 + rb + r) * FOUT + cb) = v;
    }
}

// ------- Phase 2: s_src/s_dst + exp factors (one warp per node) -------
__global__ void __launch_bounds__(256) k_score(const float* __restrict__ a_vec) {
    int gw   = (blockIdx.x * blockDim.x + threadIdx.x) >> 5;
    int lane = threadIdx.x & 31;
    if (gw >= NN) return;
    float4 w  = reinterpret_cast<const float4*>(g_Wh + (size_t)gw * FOUT)[lane];
    float4 as = reinterpret_cast<const float4*>(a_vec)[lane];
    float4 ad = reinterpret_cast<const float4*>(a_vec + FOUT)[lane];
    float ss = w.x * as.x + w.y * as.y + w.z * as.z + w.w * as.w;
    float sd = w.x * ad.x + w.y * ad.y + w.z * ad.z + w.w * ad.w;
#pragma unroll
    for (int o = 16; o > 0; o >>= 1) {
        ss += __shfl_xor_sync(0xffffffffu, ss, o);
        sd += __shfl_xor_sync(0xffffffffu, sd, o);
    }
    if (lane == 0) {
        g_ssrc[gw]  = ss;
        g_usrc[gw]  = expf(ss);
        g_u5src[gw] = expf(0.2f * ss);
        g_sdst[gw]  = sd;
        g_vdst[gw]  = expf(sd);
        g_v5dst[gw] = expf(0.2f * sd);
    }
}

// ------------- Phase 3: fused masked-softmax @ Wh (tf32 MMA) -------------
extern __shared__ float dynsmem[];

__global__ void __launch_bounds__(256) k_gat(const int* __restrict__ adj,
                                             float* __restrict__ out) {
    float* sP   = dynsmem;                 // MT x SPS  (P tile, tf32 values)
    float* sB   = dynsmem + MT * SPS;      // JT x SBS  (Wh tile, tf32 values)
    float* sDen = sB + JT * SBS;           // MT

    const int t    = threadIdx.x;
    const int lane = t & 31;
    const int w    = t >> 5;
    const int i0   = blockIdx.x * MT;
    const int jl   = lane * 4;

    // row-side constants: rows  w + 8*it  (it = 0..7)
    float ssr[8], usr[8], u5r[8];
#pragma unroll
    for (int it = 0; it < 8; it++) {
        int gr = i0 + w + 8 * it;
        ssr[it] = g_ssrc[gr];
        usr[it] = g_usrc[gr];
        u5r[it] = g_u5src[gr];
    }
    float den[8];
#pragma unroll
    for (int it = 0; it < 8; it++) den[it] = 0.f;

    float acc[8][4];
#pragma unroll
    for (int nt = 0; nt < 8; nt++)
#pragma unroll
        for (int c = 0; c < 4; c++) acc[nt][c] = 0.f;

    const int mrow = (w & 3) * 16;   // warp MMA tile: rows mrow..mrow+15
    const int ncol = (w >> 2) * 64;  //                cols ncol..ncol+63
    const int qr   = lane >> 2;      // 0..7
    const int qc   = lane & 3;       // 0..3

    for (int jt = 0; jt < NN / JT; jt++) {
        const int j0 = jt * JT;
        // per-thread j-side constants for this tile (L2-hot, shared by all CTAs)
        float4 sd  = *reinterpret_cast<const float4*>(g_sdst  + j0 + jl);
        float4 vd  = *reinterpret_cast<const float4*>(g_vdst  + j0 + jl);
        float4 v5d = *reinterpret_cast<const float4*>(g_v5dst + j0 + jl);

        __syncthreads();   // previous tile's MMA done before overwriting sP/sB

        // stage Wh tile (j0..j0+127, all 128 features) -> sB, tf32-rounded
#pragma unroll
        for (int it = 0; it < 16; it++) {
            int idx = t + 256 * it;
            int row = idx >> 5;
            int c4  = (idx & 31) * 4;
            float4 v = *reinterpret_cast<const float4*>(g_Wh + (size_t)(j0 + row) * FOUT + c4);
            v.x = to_tf32(v.x); v.y = to_tf32(v.y); v.z = to_tf32(v.z); v.w = to_tf32(v.w);
            *reinterpret_cast<float4*>(&sB[row * SBS + c4]) = v;
        }

        // P generation: thread covers rows w+8*it, cols j0+jl..jl+3
#pragma unroll
        for (int it = 0; it < 8; it++) {
            int r = w + 8 * it;
            int4 am = *reinterpret_cast<const int4*>(adj + (size_t)(i0 + r) * NN + j0 + jl);
            float x0 = ssr[it] + sd.x;
            float x1 = ssr[it] + sd.y;
            float x2 = ssr[it] + sd.z;
            float x3 = ssr[it] + sd.w;
            // exp(leaky_relu(x)) via precomputed factors: no transcendental here
            float p0 = x0 > 0.f ? usr[it] * vd.x : u5r[it] * v5d.x;
            float p1 = x1 > 0.f ? usr[it] * vd.y : u5r[it] * v5d.y;
            float p2 = x2 > 0.f ? usr[it] * vd.z : u5r[it] * v5d.z;
            float p3 = x3 > 0.f ? usr[it] * vd.w : u5r[it] * v5d.w;
            p0 = am.x > 0 ? p0 : 0.f;
            p1 = am.y > 0 ? p1 : 0.f;
            p2 = am.z > 0 ? p2 : 0.f;
            p3 = am.w > 0 ? p3 : 0.f;
            den[it] += (p0 + p1) + (p2 + p3);     // fp32-exact denominator
            float4 st;
            st.x = to_tf32(p0); st.y = to_tf32(p1);
            st.z = to_tf32(p2); st.w = to_tf32(p3);
            *reinterpret_cast<float4*>(&sP[r * SPS + jl]) = st;
        }
        __syncthreads();

        // MMA: C(64x128) += P(64x128) @ Wh(128x128), tf32
#pragma unroll
        for (int ks = 0; ks < 16; ks++) {
            const int kk = ks * 8;
            const int ar = mrow + qr;
            unsigned a0 = __float_as_uint(sP[ar * SPS + kk + qc]);
            unsigned a1 = __float_as_uint(sP[(ar + 8) * SPS + kk + qc]);
            unsigned a2 = __float_as_uint(sP[ar * SPS + kk + qc + 4]);
            unsigned a3 = __float_as_uint(sP[(ar + 8) * SPS + kk + qc + 4]);
#pragma unroll
            for (int nt = 0; nt < 8; nt++) {
                const int bc = ncol + nt * 8 + qr;
                unsigned b0 = __float_as_uint(sB[(kk + qc) * SBS + bc]);
                unsigned b1 = __float_as_uint(sB[(kk + qc + 4) * SBS + bc]);
                asm volatile(
                    "mma.sync.aligned.m16n8k8.row.col.f32.tf32.tf32.f32 "
                    "{%0,%1,%2,%3}, {%4,%5,%6,%7}, {%8,%9}, {%0,%1,%2,%3};\n"
                    : "+f"(acc[nt][0]), "+f"(acc[nt][1]),
                      "+f"(acc[nt][2]), "+f"(acc[nt][3])
                    : "r"(a0), "r"(a1), "r"(a2), "r"(a3), "r"(b0), "r"(b1));
            }
        }
    }

    // denominator: warp w owns rows w+8*it -> shuffle-reduce, publish to SMEM
#pragma unroll
    for (int it = 0; it < 8; it++) {
        float d = den[it];
#pragma unroll
        for (int o = 16; o > 0; o >>= 1) d += __shfl_xor_sync(0xffffffffu, d, o);
        if (lane == 0) sDen[w + 8 * it] = d;
    }
    __syncthreads();

    const float rd0 = 1.f / sDen[mrow + qr];
    const float rd1 = 1.f / sDen[mrow + qr + 8];
    const int   r0  = i0 + mrow + qr;
#pragma unroll
    for (int nt = 0; nt < 8; nt++) {
        int col = ncol + nt * 8 + qc * 2;
        float2 v0 = make_float2(acc[nt][0] * rd0, acc[nt][1] * rd0);
        float2 v1 = make_float2(acc[nt][2] * rd1, acc[nt][3] * rd1);
        *reinterpret_cast<float2*>(out + (size_t)r0 * FOUT + col)       = v0;
        *reinterpret_cast<float2*>(out + (size_t)(r0 + 8) * FOUT + col) = v1;
    }
}

// ---------------------------------------------------------------
extern "C" void kernel_launch(void* const* d_in, const int* in_sizes, int n_in,
                              void* d_out, int out_size) {
    const float* h   = (const float*)d_in[0];
    const int*   adj = (const int*)d_in[1];
    const float* W   = (const float*)d_in[2];
    const float* a   = (const float*)d_in[3];
    float*       out = (float*)d_out;
    (void)in_sizes; (void)n_in; (void)out_size;

    const int smem_bytes = (MT * SPS + JT * SBS + MT) * (int)sizeof(float);
    cudaFuncSetAttribute(k_gat, cudaFuncAttributeMaxDynamicSharedMemorySize, smem_bytes);

    k_wh<<<NN / MT, 256>>>(h, W);
    k_score<<<NN / 8, 256>>>(a);
    k_gat<<<NN / MT, 256, smem_bytes>>>(adj, out);
}

// round 5
// speedup vs baseline: 2.1131x; 2.1131x over previous
#include <cuda_runtime.h>
#include <cstdint>
#include <cstddef>

#define NN   8192
#define FIN  256
#define FOUT 128
#define MT   64
#define JT   128
#define SPS  132    // A tile stride: bank (4*qr+qc+kk)%32 -> conflict-free
#define SBS  136    // B tile stride: bank (8*qc+qr+c)%32  -> conflict-free
#define NTL  64     // j-tiles

__device__ float g_Wh [NN * FOUT];
__device__ float g_Whr[NN * FOUT];   // tf32-rounded copy for MMA B operand
__device__ float g_ss[NN], g_us[NN], g_u5[NN];
__device__ float g_sd[NN], g_vd[NN], g_v5[NN];

__device__ __forceinline__ float to_tf32(float x) {
    unsigned r; asm("cvt.rna.tf32.f32 %0, %1;" : "=r"(r) : "f"(x));
    return __uint_as_float(r);
}

#define CPASYNC16(dst, src) \
    asm volatile("cp.async.cg.shared.global [%0], [%1], 16;" :: "r"(dst), "l"(src))
#define CPCOMMIT() asm volatile("cp.async.commit_group;" ::: "memory")
#define CPWAIT1()  asm volatile("cp.async.wait_group 1;" ::: "memory")

// ---------------- Phase 1: Wh = h @ W^T (fp32 SIMT) ----------------
__global__ void __launch_bounds__(256) k_wh(const float* __restrict__ h,
                                            const float* __restrict__ W) {
    __shared__ float sH[32][68];
    __shared__ float sW[32][132];
    const int t = threadIdx.x, i0 = blockIdx.x * 64;
    const int rb = (t >> 5) * 8, cb = (t & 31) * 4;
    float acc[8][4];
#pragma unroll
    for (int r = 0; r < 8; r++)
#pragma unroll
        for (int c = 0; c < 4; c++) acc[r][c] = 0.f;
    for (int k0 = 0; k0 < FIN; k0 += 32) {
        __syncthreads();
#pragma unroll
        for (int it = 0; it < 2; it++) {
            int idx = t + 256 * it, row = idx >> 3, kc = (idx & 7) * 4;
            float4 v = *reinterpret_cast<const float4*>(h + (size_t)(i0 + row) * FIN + k0 + kc);
            sH[kc][row] = v.x; sH[kc + 1][row] = v.y; sH[kc + 2][row] = v.z; sH[kc + 3][row] = v.w;
        }
#pragma unroll
        for (int it = 0; it < 4; it++) {
            int idx = t + 256 * it, f = idx >> 3, kc = (idx & 7) * 4;
            float4 v = *reinterpret_cast<const float4*>(W + (size_t)f * FIN + k0 + kc);
            sW[kc][f] = v.x; sW[kc + 1][f] = v.y; sW[kc + 2][f] = v.z; sW[kc + 3][f] = v.w;
        }
        __syncthreads();
#pragma unroll
        for (int k = 0; k < 32; k++) {
            float a[8], b[4];
            *reinterpret_cast<float4*>(a)     = *reinterpret_cast<const float4*>(&sH[k][rb]);
            *reinterpret_cast<float4*>(a + 4) = *reinterpret_cast<const float4*>(&sH[k][rb + 4]);
            *reinterpret_cast<float4*>(b)     = *reinterpret_cast<const float4*>(&sW[k][cb]);
#pragma unroll
            for (int r = 0; r < 8; r++)
#pragma unroll
                for (int c = 0; c < 4; c++) acc[r][c] = fmaf(a[r], b[c], acc[r][c]);
        }
    }
#pragma unroll
    for (int r = 0; r < 8; r++) {
        float4 v  = make_float4(acc[r][0], acc[r][1], acc[r][2], acc[r][3]);
        float4 vr = make_float4(to_tf32(v.x), to_tf32(v.y), to_tf32(v.z), to_tf32(v.w));
        *reinterpret_cast<float4*>(g_Wh  + (size_t)(i0 + rb + r) * FOUT + cb) = v;
        *reinterpret_cast<float4*>(g_Whr + (size_t)(i0 + rb + r) * FOUT + cb) = vr;
    }
}

// ---------------- Phase 2: scores + exp factors ----------------
__global__ void __launch_bounds__(256) k_score(const float* __restrict__ a_vec) {
    int gw = (blockIdx.x * blockDim.x + threadIdx.x) >> 5, lane = threadIdx.x & 31;
    if (gw >= NN) return;
    float4 w  = reinterpret_cast<const float4*>(g_Wh + (size_t)gw * FOUT)[lane];
    float4 as = reinterpret_cast<const float4*>(a_vec)[lane];
    float4 ad = reinterpret_cast<const float4*>(a_vec + FOUT)[lane];
    float ss = w.x * as.x + w.y * as.y + w.z * as.z + w.w * as.w;
    float sd = w.x * ad.x + w.y * ad.y + w.z * ad.z + w.w * ad.w;
#pragma unroll
    for (int o = 16; o > 0; o >>= 1) {
        ss += __shfl_xor_sync(0xffffffffu, ss, o);
        sd += __shfl_xor_sync(0xffffffffu, sd, o);
    }
    if (lane == 0) {
        g_ss[gw] = ss; g_us[gw] = expf(ss); g_u5[gw] = expf(0.2f * ss);
        g_sd[gw] = sd; g_vd[gw] = expf(sd); g_v5[gw] = expf(0.2f * sd);
    }
}

// ------- Phase 3: fused masked-softmax @ Wh (pipelined tf32 mma.sync) -------
extern __shared__ float dynsmem[];

__global__ void __launch_bounds__(256, 1) k_gat(const int* __restrict__ adj,
                                                float* __restrict__ out) {
    float* sP   = dynsmem;                    // MT x SPS   (single buffer)
    float* sB   = dynsmem + MT * SPS;         // 2 x JT x SBS (double buffer)
    float* sDen = sB + 2 * JT * SBS;          // MT

    const int t    = threadIdx.x;
    const int lane = t & 31;
    const int w    = t >> 5;
    const int i0   = blockIdx.x * MT;
    const int jl   = lane * 4;

    const uint32_t sBu = (uint32_t)__cvta_generic_to_shared(sB);

    // row-side constants (rows w + 8*it)
    float ssr[8], usr[8], u5r[8], den[8];
#pragma unroll
    for (int it = 0; it < 8; it++) {
        int gr = i0 + w + 8 * it;
        ssr[it] = g_ss[gr]; usr[it] = g_us[gr]; u5r[it] = g_u5[gr];
        den[it] = 0.f;
    }

    float acc[8][4];
#pragma unroll
    for (int nt = 0; nt < 8; nt++)
#pragma unroll
        for (int c = 0; c < 4; c++) acc[nt][c] = 0.f;

    const int mrow = (w & 3) * 16;
    const int ncol = (w >> 2) * 64;
    const int qr   = lane >> 2;
    const int qc   = lane & 3;

    // ---- prologue: tile-0 operand prefetch + B cp.async ----
    int4  amC[8];
    float4 sdC = *reinterpret_cast<const float4*>(g_sd + jl);
    float4 vdC = *reinterpret_cast<const float4*>(g_vd + jl);
    float4 v5C = *reinterpret_cast<const float4*>(g_v5 + jl);
#pragma unroll
    for (int it = 0; it < 8; it++)
        amC[it] = *reinterpret_cast<const int4*>(adj + (size_t)(i0 + w + 8 * it) * NN + jl);
#pragma unroll
    for (int i = 0; i < 16; i++) {
        int c = t + 256 * i, r = c >> 5, q = c & 31;
        CPASYNC16(sBu + (uint32_t)(r * SBS + q * 4) * 4u, g_Whr + (size_t)r * FOUT + q * 4);
    }
    CPCOMMIT();

    for (int jt = 0; jt < NTL; jt++) {
        // ---- P-gen(jt) from registers -> sP (MMA(jt-1) done: post-MMA sync) ----
#pragma unroll
        for (int it = 0; it < 8; it++) {
            int r = w + 8 * it;
            float p0 = (ssr[it] + sdC.x) > 0.f ? usr[it] * vdC.x : u5r[it] * v5C.x;
            float p1 = (ssr[it] + sdC.y) > 0.f ? usr[it] * vdC.y : u5r[it] * v5C.y;
            float p2 = (ssr[it] + sdC.z) > 0.f ? usr[it] * vdC.z : u5r[it] * v5C.z;
            float p3 = (ssr[it] + sdC.w) > 0.f ? usr[it] * vdC.w : u5r[it] * v5C.w;
            p0 = amC[it].x > 0 ? p0 : 0.f;
            p1 = amC[it].y > 0 ? p1 : 0.f;
            p2 = amC[it].z > 0 ? p2 : 0.f;
            p3 = amC[it].w > 0 ? p3 : 0.f;
            den[it] += (p0 + p1) + (p2 + p3);
            float4 st;
            st.x = to_tf32(p0); st.y = to_tf32(p1); st.z = to_tf32(p2); st.w = to_tf32(p3);
            *reinterpret_cast<float4*>(&sP[r * SPS + jl]) = st;
        }

        // ---- prefetch tile jt+1 (B via cp.async, adj/jc via LDG) ----
        const int tn  = (jt + 1) & (NTL - 1);   // 63 -> dummy reload of tile 0
        const int j0n = tn * JT;
        const float* bsrc = g_Whr + (size_t)j0n * FOUT;
        const uint32_t sBn = sBu + (uint32_t)(((jt + 1) & 1) * JT * SBS) * 4u;
#pragma unroll
        for (int i = 0; i < 16; i++) {
            int c = t + 256 * i, r = c >> 5, q = c & 31;
            CPASYNC16(sBn + (uint32_t)(r * SBS + q * 4) * 4u, bsrc + (size_t)r * FOUT + q * 4);
        }
        CPCOMMIT();
        sdC = *reinterpret_cast<const float4*>(g_sd + j0n + jl);
        vdC = *reinterpret_cast<const float4*>(g_vd + j0n + jl);
        v5C = *reinterpret_cast<const float4*>(g_v5 + j0n + jl);
#pragma unroll
        for (int it = 0; it < 8; it++)
            amC[it] = *reinterpret_cast<const int4*>(adj + (size_t)(i0 + w + 8 * it) * NN + j0n + jl);

        // ---- wait B(jt) landed; publish sP ----
        CPWAIT1();
        __syncthreads();

        // ---- MMA(jt): C += P @ Wh ----
        const float* sBb = sB + (jt & 1) * JT * SBS;
#pragma unroll
        for (int ks = 0; ks < 16; ks++) {
            const int kk = ks * 8;
            const int ar = mrow + qr;
            unsigned a0 = __float_as_uint(sP[ar * SPS + kk + qc]);
            unsigned a1 = __float_as_uint(sP[(ar + 8) * SPS + kk + qc]);
            unsigned a2 = __float_as_uint(sP[ar * SPS + kk + qc + 4]);
            unsigned a3 = __float_as_uint(sP[(ar + 8) * SPS + kk + qc + 4]);
#pragma unroll
            for (int nt = 0; nt < 8; nt++) {
                const int bc = ncol + nt * 8 + qr;
                unsigned b0 = __float_as_uint(sBb[(kk + qc) * SBS + bc]);
                unsigned b1 = __float_as_uint(sBb[(kk + qc + 4) * SBS + bc]);
                asm volatile(
                    "mma.sync.aligned.m16n8k8.row.col.f32.tf32.tf32.f32 "
                    "{%0,%1,%2,%3}, {%4,%5,%6,%7}, {%8,%9}, {%0,%1,%2,%3};\n"
                    : "+f"(acc[nt][0]), "+f"(acc[nt][1]),
                      "+f"(acc[nt][2]), "+f"(acc[nt][3])
                    : "r"(a0), "r"(a1), "r"(a2), "r"(a3), "r"(b0), "r"(b1));
            }
        }
        __syncthreads();   // sP/sB(jt&1) free for next iteration's writers
    }

    // ---- epilogue: denominators + scaled store ----
#pragma unroll
    for (int it = 0; it < 8; it++) {
        float d = den[it];
#pragma unroll
        for (int o = 16; o > 0; o >>= 1) d += __shfl_xor_sync(0xffffffffu, d, o);
        if (lane == 0) sDen[w + 8 * it] = d;
    }
    __syncthreads();

    const float rd0 = 1.f / sDen[mrow + qr];
    const float rd1 = 1.f / sDen[mrow + qr + 8];
    const int   r0  = i0 + mrow + qr;
#pragma unroll
    for (int nt = 0; nt < 8; nt++) {
        int col = ncol + nt * 8 + qc * 2;
        float2 v0 = make_float2(acc[nt][0] * rd0, acc[nt][1] * rd0);
        float2 v1 = make_float2(acc[nt][2] * rd1, acc[nt][3] * rd1);
        *reinterpret_cast<float2*>(out + (size_t)r0 * FOUT + col)       = v0;
        *reinterpret_cast<float2*>(out + (size_t)(r0 + 8) * FOUT + col) = v1;
    }
}

// ---------------------------------------------------------------
extern "C" void kernel_launch(void* const* d_in, const int* in_sizes, int n_in,
                              void* d_out, int out_size) {
    const float* h   = (const float*)d_in[0];
    const int*   adj = (const int*)d_in[1];
    const float* W   = (const float*)d_in[2];
    const float* a   = (const float*)d_in[3];
    float*       out = (float*)d_out;
    (void)in_sizes; (void)n_in; (void)out_size;

    const int smem_bytes = (MT * SPS + 2 * JT * SBS + MT) * (int)sizeof(float);
    static int inited = 0;
    if (!inited) {
        cudaFuncSetAttribute(k_gat, cudaFuncAttributeMaxDynamicSharedMemorySize, smem_bytes);
        inited = 1;
    }
    k_wh<<<NN / 64, 256>>>(h, W);
    k_score<<<NN / 8, 256>>>(a);
    k_gat<<<NN / MT, 256, smem_bytes>>>(adj, out);
}